// round 8
// baseline (speedup 1.0000x reference)
#include <cuda_runtime.h>
#include <math.h>

#define BB 512
#define TT 1024
#define EE 64
#define HH 32
#define PP 720

typedef unsigned long long u64;

// ---------------- scratch (device globals: no allocation allowed) ----------
__device__ float g_z0[(size_t)TT * BB * HH];   // [t][b][h]
__device__ float g_hT0[BB * HH];
__device__ float g_hT1[BB * HH];
__device__ float g_ts1[(size_t)PP * BB * HH];  // [p][b][h]

// ---------------- packed fp32x2 helpers (Blackwell FFMA2) ------------------
__device__ __forceinline__ u64 pk(float a, float b) {
    u64 r; asm("mov.b64 %0, {%1,%2};" : "=l"(r) : "f"(a), "f"(b)); return r;
}
__device__ __forceinline__ float2 upk(u64 v) {
    float2 r; asm("mov.b64 {%0,%1}, %2;" : "=f"(r.x), "=f"(r.y) : "l"(v)); return r;
}
__device__ __forceinline__ u64 fma2(u64 a, u64 b, u64 c) {
    u64 d; asm("fma.rn.f32x2 %0, %1, %2, %3;" : "=l"(d) : "l"(a), "l"(b), "l"(c)); return d;
}
__device__ __forceinline__ u64 add2(u64 a, u64 b) {
    u64 d; asm("add.rn.f32x2 %0, %1, %2;" : "=l"(d) : "l"(a), "l"(b)); return d;
}

// fast tanh: tanh(x) = 1 - 2/(1+exp(2x)); exact at both saturations.
__device__ __forceinline__ float ftanh(float x) {
    float e;
    asm("ex2.approx.f32 %0, %1;" : "=f"(e) : "f"(x * 2.885390081777927f));
    return 1.0f - __fdividef(2.0f, e + 1.0f);
}

// exact-GELU via Abramowitz-Stegun 7.1.26 erf (abs err <= 1.5e-7),
// using fast intrinsics instead of libdevice erff.
__device__ __forceinline__ float gelu(float x) {
    const float u = x * 0.70710678118654752f;
    const float au = fabsf(u);
    const float t = __fdividef(1.0f, fmaf(0.3275911f, au, 1.0f));
    const float e = __expf(-u * u);
    float p = fmaf(t, 1.061405429f, -1.453152027f);
    p = fmaf(t, p, 1.421413741f);
    p = fmaf(t, p, -0.284496736f);
    p = fmaf(t, p, 0.254829592f);
    const float erf_abs = fmaf(-p * t, e, 1.0f);
    const float er = copysignf(erf_abs, u);
    return 0.5f * x * (1.0f + er);
}

// ============================================================================
// Kernel 1: z0[t][b][h] = dot(x[b][t][:], Wih0[h][:]) + (bih0+bhh0)[h]
// Weights staged transposed (WsT[e*33+h]) -> conflict-free lane reads.
// ============================================================================
__global__ __launch_bounds__(256) void k_z0(const float* __restrict__ x,
                                            const float* __restrict__ Wih0,
                                            const float* __restrict__ bih0,
                                            const float* __restrict__ bhh0) {
    __shared__ __align__(16) float Xs[64 * EE];   // 16 KB
    __shared__ float WsT[EE * 33];
    __shared__ float bs[HH];

    const int tid = threadIdx.x;
    const long R0 = (long)blockIdx.x * 64;

    {
        const float4* src = (const float4*)(x + R0 * EE);
        float4* dst = (float4*)Xs;
#pragma unroll
        for (int i = 0; i < 4; i++) dst[tid + 256 * i] = src[tid + 256 * i];
    }
    for (int i4 = tid; i4 < 512; i4 += 256) {
        float4 v = ((const float4*)Wih0)[i4];
        const int h = i4 >> 4;
        const int e0 = (i4 & 15) * 4;
        WsT[(e0 + 0) * 33 + h] = v.x;
        WsT[(e0 + 1) * 33 + h] = v.y;
        WsT[(e0 + 2) * 33 + h] = v.z;
        WsT[(e0 + 3) * 33 + h] = v.w;
    }
    if (tid < HH) bs[tid] = bih0[tid] + bhh0[tid];
    __syncthreads();

    const int h = tid & 31;
    const int rbase = tid >> 5;

    u64 wp[EE / 2];
#pragma unroll
    for (int k = 0; k < EE / 2; k++)
        wp[k] = pk(WsT[(2 * k) * 33 + h], WsT[(2 * k + 1) * 33 + h]);
    const float bias = bs[h];

#pragma unroll
    for (int rr = 0; rr < 8; rr++) {
        const int r = rbase + 8 * rr;
        u64 a = pk(bias, 0.0f), b = pk(0.0f, 0.0f);
#pragma unroll
        for (int e4 = 0; e4 < EE / 4; e4++) {
            ulonglong2 xv = *(const ulonglong2*)&Xs[r * EE + 4 * e4];  // broadcast
            a = fma2(xv.x, wp[2 * e4 + 0], a);
            b = fma2(xv.y, wp[2 * e4 + 1], b);
        }
        float2 u = upk(add2(a, b));
        const long R = R0 + r;
        const int bidx = (int)(R >> 10);
        const int t = (int)(R & 1023);
        g_z0[((long)t * BB + bidx) * HH + h] = u.x + u.y;
    }
}

// ---------------- per-row scan dots (layer0 sum, layer1 sum) ---------------
__device__ __forceinline__ void scan_dots(const float* __restrict__ shArow,
                                          const float* __restrict__ shBrow,
                                          const u64* w0p, const u64* wi1p,
                                          const u64* wh1p,
                                          float zin, float bias1,
                                          float& o0, float& o12) {
    const u64 ZZ = pk(0.0f, 0.0f);
    u64 m0a = pk(zin, 0.0f), m0b = ZZ, m0c = ZZ, m0d = ZZ;
    u64 m1a = pk(bias1, 0.0f), m1b = ZZ, m1c = ZZ, m1d = ZZ;
    u64 m2a = ZZ, m2b = ZZ, m2c = ZZ, m2d = ZZ;
#pragma unroll
    for (int q = 0; q < 4; q++) {
        ulonglong2 a0 = *(const ulonglong2*)&shArow[8 * q];
        ulonglong2 a1 = *(const ulonglong2*)&shArow[8 * q + 4];
        ulonglong2 c0 = *(const ulonglong2*)&shBrow[8 * q];
        ulonglong2 c1 = *(const ulonglong2*)&shBrow[8 * q + 4];
        m0a = fma2(a0.x, w0p[4 * q + 0], m0a);
        m0b = fma2(a0.y, w0p[4 * q + 1], m0b);
        m0c = fma2(a1.x, w0p[4 * q + 2], m0c);
        m0d = fma2(a1.y, w0p[4 * q + 3], m0d);
        m1a = fma2(a0.x, wi1p[4 * q + 0], m1a);
        m1b = fma2(a0.y, wi1p[4 * q + 1], m1b);
        m1c = fma2(a1.x, wi1p[4 * q + 2], m1c);
        m1d = fma2(a1.y, wi1p[4 * q + 3], m1d);
        m2a = fma2(c0.x, wh1p[4 * q + 0], m2a);
        m2b = fma2(c0.y, wh1p[4 * q + 1], m2b);
        m2c = fma2(c1.x, wh1p[4 * q + 2], m2c);
        m2d = fma2(c1.y, wh1p[4 * q + 3], m2d);
    }
    float2 r0 = upk(add2(add2(m0a, m0b), add2(m0c, m0d)));
    float2 r1 = upk(add2(add2(m1a, m1b), add2(m1c, m1d)));
    float2 r2 = upk(add2(add2(m2a, m2b), add2(m2c, m2d)));
    o0 = r0.x + r0.y;
    o12 = (r1.x + r1.y) + (r2.x + r2.y);
}

// layer-1-only dot (epilogue)
__device__ __forceinline__ float scan_dot1(const float* __restrict__ shArow,
                                           const float* __restrict__ shBrow,
                                           const u64* wi1p, const u64* wh1p,
                                           float bias1) {
    const u64 ZZ = pk(0.0f, 0.0f);
    u64 m1a = pk(bias1, 0.0f), m1b = ZZ, m2a = ZZ, m2b = ZZ;
#pragma unroll
    for (int q = 0; q < 8; q++) {
        ulonglong2 a = *(const ulonglong2*)&shArow[4 * q];
        ulonglong2 c = *(const ulonglong2*)&shBrow[4 * q];
        m1a = fma2(a.x, wi1p[2 * q], m1a);  m1b = fma2(a.y, wi1p[2 * q + 1], m1b);
        m2a = fma2(c.x, wh1p[2 * q], m2a);  m2b = fma2(c.y, wh1p[2 * q + 1], m2b);
    }
    float2 r1 = upk(add2(m1a, m1b));
    float2 r2 = upk(add2(m2a, m2b));
    return (r1.x + r1.y) + (r2.x + r2.y);
}

#define LOAD_SCAN_WEIGHTS(W0, WI1, WH1)                                        \
    u64 w0p[16], wi1p[16], wh1p[16];                                           \
    _Pragma("unroll")                                                          \
    for (int i = 0; i < 8; i++) {                                              \
        float4 v0 = *(const float4*)&(W0)[lane * HH + 4 * i];                  \
        float4 v1 = *(const float4*)&(WI1)[lane * HH + 4 * i];                 \
        float4 v2 = *(const float4*)&(WH1)[lane * HH + 4 * i];                 \
        w0p[2 * i] = pk(v0.x, v0.y);  w0p[2 * i + 1] = pk(v0.z, v0.w);         \
        wi1p[2 * i] = pk(v1.x, v1.y); wi1p[2 * i + 1] = pk(v1.z, v1.w);        \
        wh1p[2 * i] = pk(v2.x, v2.y); wh1p[2 * i + 1] = pk(v2.z, v2.w);        \
    }

// ============================================================================
// Kernel 2: encoder 2-layer scan, TWO rows per warp (shared weight registers,
// overlapped latency chains). 2 warps/block (64 thr), grid 128 -> 4 rows/block.
// Layer 1 lagged one step; unroll-4; depth-4 z prefetch.
// ============================================================================
__global__ __launch_bounds__(64) void k_enc(const float* __restrict__ Whh0,
                                            const float* __restrict__ Wih1,
                                            const float* __restrict__ Whh1,
                                            const float* __restrict__ bih1,
                                            const float* __restrict__ bhh1) {
    __shared__ __align__(16) float shA[2][4][HH];
    __shared__ __align__(16) float shB[2][4][HH];

    const int lane = threadIdx.x & 31;
    const int w = threadIdx.x >> 5;           // 0..1
    const int row0 = 2 * w;                   // local rows 2w, 2w+1
    const int b0 = blockIdx.x * 4 + row0;

    LOAD_SCAN_WEIGHTS(Whh0, Wih1, Whh1)
    const float bias1 = bih1[lane] + bhh1[lane];

    shA[0][row0 + 0][lane] = 0.0f; shB[0][row0 + 0][lane] = 0.0f;
    shA[0][row0 + 1][lane] = 0.0f; shB[0][row0 + 1][lane] = 0.0f;
    __syncwarp();

    const int ST = BB * HH;
    const float* zp0 = g_z0 + (long)(b0 + 0) * HH + lane;
    const float* zp1 = g_z0 + (long)(b0 + 1) * HH + lane;

    float zbuf0[4], zbuf1[4];
#pragma unroll
    for (int i = 0; i < 4; i++) {
        zbuf0[i] = zp0[(long)i * ST];
        zbuf1[i] = zp1[(long)i * ST];
    }

    float h0last0 = 0.0f, h0last1 = 0.0f;

    for (int t0 = 0; t0 < TT; t0 += 4) {
        const bool pf = (t0 + 4 < TT);
#pragma unroll
        for (int u = 0; u < 4; u++) {
            const int t = t0 + u;
            const int cur = u & 1, nxt = cur ^ 1;

            const float zin0 = zbuf0[u], zin1 = zbuf1[u];
            if (pf) {
                zbuf0[u] = zp0[(long)(t + 4) * ST];
                zbuf1[u] = zp1[(long)(t + 4) * ST];
            }

            float o0a, o12a, o0b, o12b;
            scan_dots(shA[cur][row0 + 0], shB[cur][row0 + 0],
                      w0p, wi1p, wh1p, zin0, bias1, o0a, o12a);
            scan_dots(shA[cur][row0 + 1], shB[cur][row0 + 1],
                      w0p, wi1p, wh1p, zin1, bias1, o0b, o12b);

            const float h0a = ftanh(o0a);
            const float h0b = ftanh(o0b);
            const float h1a = (t > 0) ? ftanh(o12a) : 0.0f;
            const float h1b = (t > 0) ? ftanh(o12b) : 0.0f;

            shA[nxt][row0 + 0][lane] = h0a;  shB[nxt][row0 + 0][lane] = h1a;
            shA[nxt][row0 + 1][lane] = h0b;  shB[nxt][row0 + 1][lane] = h1b;
            h0last0 = h0a; h0last1 = h0b;
            __syncwarp();
        }
    }

    // epilogue: h1[T-1] from shA[0]=h0[T-1], shB[0]=h1[T-2]  (TT % 4 == 0)
    g_hT0[(b0 + 0) * HH + lane] = h0last0;
    g_hT0[(b0 + 1) * HH + lane] = h0last1;
    g_hT1[(b0 + 0) * HH + lane] =
        ftanh(scan_dot1(shA[0][row0 + 0], shB[0][row0 + 0], wi1p, wh1p, bias1));
    g_hT1[(b0 + 1) * HH + lane] =
        ftanh(scan_dot1(shA[0][row0 + 1], shB[0][row0 + 1], wi1p, wh1p, bias1));
}

// ============================================================================
// Kernel 3: transition 2-layer scan (layer-0 input = const bias), two rows
// per warp, 2 warps/block, grid 128.
// ============================================================================
__global__ __launch_bounds__(64) void k_trans(const float* __restrict__ Whh0,
                                              const float* __restrict__ bih0,
                                              const float* __restrict__ bhh0,
                                              const float* __restrict__ Wih1,
                                              const float* __restrict__ Whh1,
                                              const float* __restrict__ bih1,
                                              const float* __restrict__ bhh1) {
    __shared__ __align__(16) float shA[2][4][HH];
    __shared__ __align__(16) float shB[2][4][HH];

    const int lane = threadIdx.x & 31;
    const int w = threadIdx.x >> 5;
    const int row0 = 2 * w;
    const int b0 = blockIdx.x * 4 + row0;

    LOAD_SCAN_WEIGHTS(Whh0, Wih1, Whh1)
    const float bias0 = bih0[lane] + bhh0[lane];
    const float bias1 = bih1[lane] + bhh1[lane];
    const float hT1a = g_hT1[(b0 + 0) * HH + lane];
    const float hT1b = g_hT1[(b0 + 1) * HH + lane];

    shA[0][row0 + 0][lane] = g_hT0[(b0 + 0) * HH + lane];
    shA[0][row0 + 1][lane] = g_hT0[(b0 + 1) * HH + lane];
    shB[0][row0 + 0][lane] = hT1a;
    shB[0][row0 + 1][lane] = hT1b;
    __syncwarp();

    const int ST = BB * HH;
    float* tp0 = g_ts1 + (long)(b0 + 0) * HH + lane;
    float* tp1 = g_ts1 + (long)(b0 + 1) * HH + lane;

    for (int p0 = 0; p0 < PP; p0 += 4) {
#pragma unroll
        for (int u = 0; u < 4; u++) {
            const int p = p0 + u;
            const int cur = u & 1, nxt = cur ^ 1;

            float o0a, o12a, o0b, o12b;
            scan_dots(shA[cur][row0 + 0], shB[cur][row0 + 0],
                      w0p, wi1p, wh1p, bias0, bias1, o0a, o12a);
            scan_dots(shA[cur][row0 + 1], shB[cur][row0 + 1],
                      w0p, wi1p, wh1p, bias0, bias1, o0b, o12b);

            const float h0a = ftanh(o0a);
            const float h0b = ftanh(o0b);
            float h1a, h1b;
            if (p > 0) {
                h1a = ftanh(o12a);
                h1b = ftanh(o12b);
                tp0[(long)(p - 1) * ST] = h1a;
                tp1[(long)(p - 1) * ST] = h1b;
            } else {
                h1a = hT1a; h1b = hT1b;
            }

            shA[nxt][row0 + 0][lane] = h0a;  shB[nxt][row0 + 0][lane] = h1a;
            shA[nxt][row0 + 1][lane] = h0b;  shB[nxt][row0 + 1][lane] = h1b;
            __syncwarp();
        }
    }

    // epilogue: t1[P-1]  (PP % 4 == 0 -> final state in buffer 0)
    tp0[(long)(PP - 1) * ST] =
        ftanh(scan_dot1(shA[0][row0 + 0], shB[0][row0 + 0], wi1p, wh1p, bias1));
    tp1[(long)(PP - 1) * ST] =
        ftanh(scan_dot1(shA[0][row0 + 1], shB[0][row0 + 1], wi1p, wh1p, bias1));
}

// ============================================================================
// Kernel 4: observation MLP, tiled GEMM chain (R4-verified config) + fast gelu.
// ============================================================================
#define MLP_SMEM_FLOATS (4096 + 2304 + 4352 + 8192 + 128)

__global__ __launch_bounds__(256, 2) void k_mlp(const float* __restrict__ W1,
                                                const float* __restrict__ b1,
                                                const float* __restrict__ W2,
                                                const float* __restrict__ b2,
                                                float* __restrict__ out) {
    extern __shared__ __align__(16) float sm[];
    float* Xs  = sm;                  // [128][32]
    float* W1s = sm + 4096;           // [64][36]
    float* W2s = sm + 6400;           // [64][68]
    float* Gs  = sm + 10752;          // [128][64]
    float* b1s = sm + 18944;
    float* b2s = sm + 19008;

    const int tid = threadIdx.x;
    const int tx = tid & 15;          // col: e_j = tx + 16*j
    const int ty = tid >> 4;          // rows 8*ty .. 8*ty+7
    const int p0 = blockIdx.x * 16;
    const int b0 = blockIdx.y * 8;

    for (int i4 = tid; i4 < 1024; i4 += 256) {
        const int r = i4 >> 3, c4 = i4 & 7;
        const int bl = r >> 4, pl = r & 15;
        ((float4*)Xs)[i4] =
            *(const float4*)&g_ts1[((long)(p0 + pl) * BB + (b0 + bl)) * HH + 4 * c4];
    }
    for (int i4 = tid; i4 < 512; i4 += 256) {      // W1 [64][32] -> [64][36]
        const int j = i4 >> 3, k4 = i4 & 7;
        ((float4*)W1s)[j * 9 + k4] = ((const float4*)W1)[i4];
    }
    for (int i4 = tid; i4 < 1024; i4 += 256) {     // W2 [64][64] -> [64][68]
        const int e = i4 >> 4, j4 = i4 & 15;
        ((float4*)W2s)[e * 17 + j4] = ((const float4*)W2)[i4];
    }
    if (tid < 64) b1s[tid] = b1[tid];
    else if (tid < 128) b2s[tid - 64] = b2[tid - 64];
    __syncthreads();

    // ---------------- phase 1: G = gelu(X @ W1^T + b1) ----------------
    u64 acc[8][4];
#pragma unroll
    for (int i = 0; i < 8; i++)
#pragma unroll
        for (int j = 0; j < 4; j++) acc[i][j] = pk(b1s[tx + 16 * j], 0.0f);

#pragma unroll
    for (int k4 = 0; k4 < 8; k4++) {
        ulonglong2 wv[4];
#pragma unroll
        for (int j = 0; j < 4; j++)
            wv[j] = *(const ulonglong2*)&W1s[(tx + 16 * j) * 36 + 4 * k4];
#pragma unroll
        for (int i = 0; i < 8; i++) {
            ulonglong2 xv = *(const ulonglong2*)&Xs[(8 * ty + i) * 32 + 4 * k4];
#pragma unroll
            for (int j = 0; j < 4; j++) {
                acc[i][j] = fma2(xv.x, wv[j].x, acc[i][j]);
                acc[i][j] = fma2(xv.y, wv[j].y, acc[i][j]);
            }
        }
    }

#pragma unroll
    for (int i = 0; i < 8; i++) {
#pragma unroll
        for (int j = 0; j < 4; j++) {
            float2 uj = upk(acc[i][j]);
            Gs[(8 * ty + i) * 64 + tx + 16 * j] = gelu(uj.x + uj.y);
        }
    }
    __syncthreads();

    // ---------------- phase 2: Y = G @ W2^T + b2 ----------------
#pragma unroll
    for (int i = 0; i < 8; i++)
#pragma unroll
        for (int j = 0; j < 4; j++) acc[i][j] = pk(b2s[tx + 16 * j], 0.0f);

#pragma unroll
    for (int k4 = 0; k4 < 16; k4++) {
        ulonglong2 wv[4];
#pragma unroll
        for (int j = 0; j < 4; j++)
            wv[j] = *(const ulonglong2*)&W2s[(tx + 16 * j) * 68 + 4 * k4];
#pragma unroll
        for (int i = 0; i < 8; i++) {
            ulonglong2 gv = *(const ulonglong2*)&Gs[(8 * ty + i) * 64 + 4 * k4];
#pragma unroll
            for (int j = 0; j < 4; j++) {
                acc[i][j] = fma2(gv.x, wv[j].x, acc[i][j]);
                acc[i][j] = fma2(gv.y, wv[j].y, acc[i][j]);
            }
        }
    }

    float y[8][4];
#pragma unroll
    for (int i = 0; i < 8; i++)
#pragma unroll
        for (int j = 0; j < 4; j++) {
            float2 uj = upk(acc[i][j]);
            y[i][j] = uj.x + uj.y;
        }

    const int bl = ty >> 1;
    const int plb = (ty & 1) * 8;
    float* ob = out + (long)(b0 + bl) * EE * PP + p0 + plb;
#pragma unroll
    for (int j = 0; j < 4; j++) {
        const int e = tx + 16 * j;
#pragma unroll
        for (int q = 0; q < 2; q++) {
            float4 v;
            v.x = y[4 * q + 0][j]; v.y = y[4 * q + 1][j];
            v.z = y[4 * q + 2][j]; v.w = y[4 * q + 3][j];
            *(float4*)&ob[(long)e * PP + 4 * q] = v;
        }
    }
}

// ============================================================================
extern "C" void kernel_launch(void* const* d_in, const int* in_sizes, int n_in,
                              void* d_out, int out_size) {
    (void)in_sizes; (void)n_in; (void)out_size;
    const float* x      = (const float*)d_in[0];
    const float* e_Wih0 = (const float*)d_in[1];
    const float* e_Whh0 = (const float*)d_in[2];
    const float* e_bih0 = (const float*)d_in[3];
    const float* e_bhh0 = (const float*)d_in[4];
    const float* e_Wih1 = (const float*)d_in[5];
    const float* e_Whh1 = (const float*)d_in[6];
    const float* e_bih1 = (const float*)d_in[7];
    const float* e_bhh1 = (const float*)d_in[8];
    // d_in[9] = t_Wih0: unused (transition input is zeros)
    const float* t_Whh0 = (const float*)d_in[10];
    const float* t_bih0 = (const float*)d_in[11];
    const float* t_bhh0 = (const float*)d_in[12];
    const float* t_Wih1 = (const float*)d_in[13];
    const float* t_Whh1 = (const float*)d_in[14];
    const float* t_bih1 = (const float*)d_in[15];
    const float* t_bhh1 = (const float*)d_in[16];
    const float* o_W1   = (const float*)d_in[17];
    const float* o_b1   = (const float*)d_in[18];
    const float* o_W2   = (const float*)d_in[19];
    const float* o_b2   = (const float*)d_in[20];
    float* out = (float*)d_out;

    cudaFuncSetAttribute(k_mlp, cudaFuncAttributeMaxDynamicSharedMemorySize,
                         MLP_SMEM_FLOATS * 4);

    k_z0<<<(BB * TT) / 64, 256>>>(x, e_Wih0, e_bih0, e_bhh0);
    k_enc<<<BB / 4, 64>>>(e_Whh0, e_Wih1, e_Whh1, e_bih1, e_bhh1);
    k_trans<<<BB / 4, 64>>>(t_Whh0, t_bih0, t_bhh0, t_Wih1, t_Whh1, t_bih1, t_bhh1);
    dim3 g(PP / 16, BB / 8);
    k_mlp<<<g, 256, MLP_SMEM_FLOATS * 4>>>(o_W1, o_b1, o_W2, o_b2, out);
}

// round 9
// speedup vs baseline: 1.4623x; 1.4623x over previous
#include <cuda_runtime.h>
#include <math.h>

#define BB 512
#define TT 1024
#define EE 64
#define HH 32
#define PP 720

typedef unsigned long long u64;

// ---------------- scratch (device globals: no allocation allowed) ----------
__device__ float g_z0[(size_t)TT * BB * HH];   // [t][b][h]
__device__ float g_ts1[(size_t)PP * BB * HH];  // [p][b][h]

// compiler-only memory barrier: step body is convergent single-warp SASS, so
// STS->LDS cross-lane visibility holds in program order; this just stops
// NVVM/ptxas from reordering the shared accesses. Replaces WARPSYNC (~23cyc).
#define WBAR() asm volatile("" ::: "memory")

// ---------------- packed fp32x2 helpers (Blackwell FFMA2) ------------------
__device__ __forceinline__ u64 pk(float a, float b) {
    u64 r; asm("mov.b64 %0, {%1,%2};" : "=l"(r) : "f"(a), "f"(b)); return r;
}
__device__ __forceinline__ float2 upk(u64 v) {
    float2 r; asm("mov.b64 {%0,%1}, %2;" : "=f"(r.x), "=f"(r.y) : "l"(v)); return r;
}
__device__ __forceinline__ u64 fma2(u64 a, u64 b, u64 c) {
    u64 d; asm("fma.rn.f32x2 %0, %1, %2, %3;" : "=l"(d) : "l"(a), "l"(b), "l"(c)); return d;
}
__device__ __forceinline__ u64 add2(u64 a, u64 b) {
    u64 d; asm("add.rn.f32x2 %0, %1, %2;" : "=l"(d) : "l"(a), "l"(b)); return d;
}

// fast tanh: tanh(x) = 1 - 2/(1+exp(2x)); exact at both saturations.
__device__ __forceinline__ float ftanh(float x) {
    float e;
    asm("ex2.approx.f32 %0, %1;" : "=f"(e) : "f"(x * 2.885390081777927f));
    return 1.0f - __fdividef(2.0f, e + 1.0f);
}

// exact-GELU via Abramowitz-Stegun 7.1.26 erf (abs err <= 1.5e-7).
__device__ __forceinline__ float gelu(float x) {
    const float u = x * 0.70710678118654752f;
    const float au = fabsf(u);
    const float t = __fdividef(1.0f, fmaf(0.3275911f, au, 1.0f));
    const float e = __expf(-u * u);
    float p = fmaf(t, 1.061405429f, -1.453152027f);
    p = fmaf(t, p, 1.421413741f);
    p = fmaf(t, p, -0.284496736f);
    p = fmaf(t, p, 0.254829592f);
    const float erf_abs = fmaf(-p * t, e, 1.0f);
    const float er = copysignf(erf_abs, u);
    return 0.5f * x * (1.0f + er);
}

// ============================================================================
// Kernel 1: z0[t][b][h] = dot(x[b][t][:], Wih0[h][:]) + (bih0+bhh0)[h]
// Weights staged transposed (WsT[e*33+h]) -> conflict-free lane reads.
// ============================================================================
__global__ __launch_bounds__(256) void k_z0(const float* __restrict__ x,
                                            const float* __restrict__ Wih0,
                                            const float* __restrict__ bih0,
                                            const float* __restrict__ bhh0) {
    __shared__ __align__(16) float Xs[64 * EE];   // 16 KB
    __shared__ float WsT[EE * 33];
    __shared__ float bs[HH];

    const int tid = threadIdx.x;
    const long R0 = (long)blockIdx.x * 64;

    {
        const float4* src = (const float4*)(x + R0 * EE);
        float4* dst = (float4*)Xs;
#pragma unroll
        for (int i = 0; i < 4; i++) dst[tid + 256 * i] = src[tid + 256 * i];
    }
    for (int i4 = tid; i4 < 512; i4 += 256) {
        float4 v = ((const float4*)Wih0)[i4];
        const int h = i4 >> 4;
        const int e0 = (i4 & 15) * 4;
        WsT[(e0 + 0) * 33 + h] = v.x;
        WsT[(e0 + 1) * 33 + h] = v.y;
        WsT[(e0 + 2) * 33 + h] = v.z;
        WsT[(e0 + 3) * 33 + h] = v.w;
    }
    if (tid < HH) bs[tid] = bih0[tid] + bhh0[tid];
    __syncthreads();

    const int h = tid & 31;
    const int rbase = tid >> 5;

    u64 wp[EE / 2];
#pragma unroll
    for (int k = 0; k < EE / 2; k++)
        wp[k] = pk(WsT[(2 * k) * 33 + h], WsT[(2 * k + 1) * 33 + h]);
    const float bias = bs[h];

#pragma unroll
    for (int rr = 0; rr < 8; rr++) {
        const int r = rbase + 8 * rr;
        u64 a = pk(bias, 0.0f), b = pk(0.0f, 0.0f);
#pragma unroll
        for (int e4 = 0; e4 < EE / 4; e4++) {
            ulonglong2 xv = *(const ulonglong2*)&Xs[r * EE + 4 * e4];  // broadcast
            a = fma2(xv.x, wp[2 * e4 + 0], a);
            b = fma2(xv.y, wp[2 * e4 + 1], b);
        }
        float2 u = upk(add2(a, b));
        const long R = R0 + r;
        const int bidx = (int)(R >> 10);
        const int t = (int)(R & 1023);
        g_z0[((long)t * BB + bidx) * HH + h] = u.x + u.y;
    }
}

// ---------------- shared scan-step macro (4-acc split chains) --------------
#define SCAN_DOT(CUR)                                                          \
    u64 m0a = pk(zin, 0.0f), m0b = ZZ, m0c = ZZ, m0d = ZZ;                     \
    u64 m1a = pk(bias1, 0.0f), m1b = ZZ, m1c = ZZ, m1d = ZZ;                   \
    u64 m2a = ZZ, m2b = ZZ, m2c = ZZ, m2d = ZZ;                                \
    _Pragma("unroll")                                                          \
    for (int q = 0; q < 4; q++) {                                              \
        ulonglong2 a0 = *(const ulonglong2*)&shA[CUR][w][8 * q];               \
        ulonglong2 a1 = *(const ulonglong2*)&shA[CUR][w][8 * q + 4];           \
        ulonglong2 c0 = *(const ulonglong2*)&shB[CUR][w][8 * q];               \
        ulonglong2 c1 = *(const ulonglong2*)&shB[CUR][w][8 * q + 4];           \
        m0a = fma2(a0.x, w0p[4 * q + 0], m0a);                                 \
        m0b = fma2(a0.y, w0p[4 * q + 1], m0b);                                 \
        m0c = fma2(a1.x, w0p[4 * q + 2], m0c);                                 \
        m0d = fma2(a1.y, w0p[4 * q + 3], m0d);                                 \
        m1a = fma2(a0.x, wi1p[4 * q + 0], m1a);                                \
        m1b = fma2(a0.y, wi1p[4 * q + 1], m1b);                                \
        m1c = fma2(a1.x, wi1p[4 * q + 2], m1c);                                \
        m1d = fma2(a1.y, wi1p[4 * q + 3], m1d);                                \
        m2a = fma2(c0.x, wh1p[4 * q + 0], m2a);                                \
        m2b = fma2(c0.y, wh1p[4 * q + 1], m2b);                                \
        m2c = fma2(c1.x, wh1p[4 * q + 2], m2c);                                \
        m2d = fma2(c1.y, wh1p[4 * q + 3], m2d);                                \
    }                                                                          \
    float2 r0 = upk(add2(add2(m0a, m0b), add2(m0c, m0d)));                     \
    float2 r1 = upk(add2(add2(m1a, m1b), add2(m1c, m1d)));                     \
    float2 r2 = upk(add2(add2(m2a, m2b), add2(m2c, m2d)));

// assign (not declare) the three packed weight rows
#define ASSIGN_SCAN_WEIGHTS(W0, WI1, WH1)                                      \
    _Pragma("unroll")                                                          \
    for (int i = 0; i < 8; i++) {                                              \
        float4 v0 = *(const float4*)&(W0)[lane * HH + 4 * i];                  \
        float4 v1 = *(const float4*)&(WI1)[lane * HH + 4 * i];                 \
        float4 v2 = *(const float4*)&(WH1)[lane * HH + 4 * i];                 \
        w0p[2 * i] = pk(v0.x, v0.y);  w0p[2 * i + 1] = pk(v0.z, v0.w);         \
        wi1p[2 * i] = pk(v1.x, v1.y); wi1p[2 * i + 1] = pk(v1.z, v1.w);        \
        wh1p[2 * i] = pk(v2.x, v2.y); wh1p[2 * i + 1] = pk(v2.z, v2.w);        \
    }

// layer-1-only dot (epilogues)
__device__ __forceinline__ float scan_dot1(const float* __restrict__ shArow,
                                           const float* __restrict__ shBrow,
                                           const u64* wi1p, const u64* wh1p,
                                           float bias1) {
    const u64 ZZ = pk(0.0f, 0.0f);
    u64 m1a = pk(bias1, 0.0f), m1b = ZZ, m2a = ZZ, m2b = ZZ;
#pragma unroll
    for (int q = 0; q < 8; q++) {
        ulonglong2 a = *(const ulonglong2*)&shArow[4 * q];
        ulonglong2 c = *(const ulonglong2*)&shBrow[4 * q];
        m1a = fma2(a.x, wi1p[2 * q], m1a);  m1b = fma2(a.y, wi1p[2 * q + 1], m1b);
        m2a = fma2(c.x, wh1p[2 * q], m2a);  m2b = fma2(c.y, wh1p[2 * q + 1], m2b);
    }
    float2 r1 = upk(add2(m1a, m1b));
    float2 r2 = upk(add2(m2a, m2b));
    return (r1.x + r1.y) + (r2.x + r2.y);
}

// ============================================================================
// Kernel 2: FUSED encoder + transition scans. One warp per batch row,
// 4 warps/block, grid 128 (full SM spread). Layer 1 lagged one step;
// unroll-8; depth-8 z prefetch; compiler barrier instead of WARPSYNC.
// Encoder final states stay in registers for the transition phase.
// ============================================================================
__global__ __launch_bounds__(128) void k_scan(
    const float* __restrict__ eWhh0, const float* __restrict__ eWih1,
    const float* __restrict__ eWhh1, const float* __restrict__ ebih1,
    const float* __restrict__ ebhh1,
    const float* __restrict__ tWhh0, const float* __restrict__ tbih0,
    const float* __restrict__ tbhh0, const float* __restrict__ tWih1,
    const float* __restrict__ tWhh1, const float* __restrict__ tbih1,
    const float* __restrict__ tbhh1) {
    __shared__ __align__(16) float shA[2][4][HH];
    __shared__ __align__(16) float shB[2][4][HH];

    const int lane = threadIdx.x & 31;
    const int w = threadIdx.x >> 5;
    const int b = blockIdx.x * 4 + w;
    const u64 ZZ = pk(0.0f, 0.0f);
    const int ST = BB * HH;

    u64 w0p[16], wi1p[16], wh1p[16];
    ASSIGN_SCAN_WEIGHTS(eWhh0, eWih1, eWhh1)
    float bias1 = ebih1[lane] + ebhh1[lane];

    shA[0][w][lane] = 0.0f;
    shB[0][w][lane] = 0.0f;
    WBAR();

    // ---------------- phase 1: encoder (1024 steps) ----------------
    const float* zp = g_z0 + (long)b * HH + lane;

    float zbuf[8];
#pragma unroll
    for (int i = 0; i < 8; i++) zbuf[i] = zp[(long)i * ST];

    float h0last = 0.0f;

    for (int t0 = 0; t0 < TT; t0 += 8) {
        const bool pf = (t0 + 8 < TT);
#pragma unroll
        for (int u = 0; u < 8; u++) {
            const int t = t0 + u;
            const int cur = u & 1, nxt = cur ^ 1;
            const float zin = zbuf[u];
            if (pf) zbuf[u] = zp[(long)(t + 8) * ST];

            SCAN_DOT(cur)

            const float h0v = ftanh(r0.x + r0.y);
            const float h1v = (t > 0) ? ftanh((r1.x + r1.y) + (r2.x + r2.y)) : 0.0f;
            shA[nxt][w][lane] = h0v;   // h0[t]
            shB[nxt][w][lane] = h1v;   // h1[t-1]
            h0last = h0v;
            WBAR();
        }
    }

    // encoder epilogue: h1[T-1] from shA[0]=h0[T-1], shB[0]=h1[T-2]
    const float hT0 = h0last;
    const float hT1 = ftanh(scan_dot1(shA[0][w], shB[0][w], wi1p, wh1p, bias1));

    // ---------------- phase 2: transition (720 steps) ----------------
    ASSIGN_SCAN_WEIGHTS(tWhh0, tWih1, tWhh1)
    const float bias0 = tbih0[lane] + tbhh0[lane];
    bias1 = tbih1[lane] + tbhh1[lane];

    shA[0][w][lane] = hT0;   // t0[-1]
    shB[0][w][lane] = hT1;   // t1[-1]
    WBAR();

    float* tp = g_ts1 + (long)b * HH + lane;

    for (int p0 = 0; p0 < PP; p0 += 8) {
#pragma unroll
        for (int u = 0; u < 8; u++) {
            const int p = p0 + u;
            const int cur = u & 1, nxt = cur ^ 1;
            const float zin = bias0;

            SCAN_DOT(cur)

            const float h0v = ftanh(r0.x + r0.y);                      // t0[p]
            const float h1v = ftanh((r1.x + r1.y) + (r2.x + r2.y));    // t1[p-1]
            if (p > 0) tp[(long)(p - 1) * ST] = h1v;
            shA[nxt][w][lane] = h0v;
            shB[nxt][w][lane] = (p > 0) ? h1v : hT1;
            WBAR();
        }
    }

    // transition epilogue: t1[P-1] from shA[0]=t0[P-1], shB[0]=t1[P-2]
    tp[(long)(PP - 1) * ST] =
        ftanh(scan_dot1(shA[0][w], shB[0][w], wi1p, wh1p, bias1));
}

// ============================================================================
// Kernel 3: observation MLP, tiled GEMM chain (R4-verified config) + fast gelu.
// ============================================================================
#define MLP_SMEM_FLOATS (4096 + 2304 + 4352 + 8192 + 128)

__global__ __launch_bounds__(256, 2) void k_mlp(const float* __restrict__ W1,
                                                const float* __restrict__ b1,
                                                const float* __restrict__ W2,
                                                const float* __restrict__ b2,
                                                float* __restrict__ out) {
    extern __shared__ __align__(16) float sm[];
    float* Xs  = sm;                  // [128][32]
    float* W1s = sm + 4096;           // [64][36]
    float* W2s = sm + 6400;           // [64][68]
    float* Gs  = sm + 10752;          // [128][64]
    float* b1s = sm + 18944;
    float* b2s = sm + 19008;

    const int tid = threadIdx.x;
    const int tx = tid & 15;          // col: e_j = tx + 16*j
    const int ty = tid >> 4;          // rows 8*ty .. 8*ty+7
    const int p0 = blockIdx.x * 16;
    const int b0 = blockIdx.y * 8;

    for (int i4 = tid; i4 < 1024; i4 += 256) {
        const int r = i4 >> 3, c4 = i4 & 7;
        const int bl = r >> 4, pl = r & 15;
        ((float4*)Xs)[i4] =
            *(const float4*)&g_ts1[((long)(p0 + pl) * BB + (b0 + bl)) * HH + 4 * c4];
    }
    for (int i4 = tid; i4 < 512; i4 += 256) {      // W1 [64][32] -> [64][36]
        const int j = i4 >> 3, k4 = i4 & 7;
        ((float4*)W1s)[j * 9 + k4] = ((const float4*)W1)[i4];
    }
    for (int i4 = tid; i4 < 1024; i4 += 256) {     // W2 [64][64] -> [64][68]
        const int e = i4 >> 4, j4 = i4 & 15;
        ((float4*)W2s)[e * 17 + j4] = ((const float4*)W2)[i4];
    }
    if (tid < 64) b1s[tid] = b1[tid];
    else if (tid < 128) b2s[tid - 64] = b2[tid - 64];
    __syncthreads();

    // ---------------- phase 1: G = gelu(X @ W1^T + b1) ----------------
    u64 acc[8][4];
#pragma unroll
    for (int i = 0; i < 8; i++)
#pragma unroll
        for (int j = 0; j < 4; j++) acc[i][j] = pk(b1s[tx + 16 * j], 0.0f);

#pragma unroll
    for (int k4 = 0; k4 < 8; k4++) {
        ulonglong2 wv[4];
#pragma unroll
        for (int j = 0; j < 4; j++)
            wv[j] = *(const ulonglong2*)&W1s[(tx + 16 * j) * 36 + 4 * k4];
#pragma unroll
        for (int i = 0; i < 8; i++) {
            ulonglong2 xv = *(const ulonglong2*)&Xs[(8 * ty + i) * 32 + 4 * k4];
#pragma unroll
            for (int j = 0; j < 4; j++) {
                acc[i][j] = fma2(xv.x, wv[j].x, acc[i][j]);
                acc[i][j] = fma2(xv.y, wv[j].y, acc[i][j]);
            }
        }
    }

#pragma unroll
    for (int i = 0; i < 8; i++) {
#pragma unroll
        for (int j = 0; j < 4; j++) {
            float2 uj = upk(acc[i][j]);
            Gs[(8 * ty + i) * 64 + tx + 16 * j] = gelu(uj.x + uj.y);
        }
    }
    __syncthreads();

    // ---------------- phase 2: Y = G @ W2^T + b2 ----------------
#pragma unroll
    for (int i = 0; i < 8; i++)
#pragma unroll
        for (int j = 0; j < 4; j++) acc[i][j] = pk(b2s[tx + 16 * j], 0.0f);

#pragma unroll
    for (int k4 = 0; k4 < 16; k4++) {
        ulonglong2 wv[4];
#pragma unroll
        for (int j = 0; j < 4; j++)
            wv[j] = *(const ulonglong2*)&W2s[(tx + 16 * j) * 68 + 4 * k4];
#pragma unroll
        for (int i = 0; i < 8; i++) {
            ulonglong2 gv = *(const ulonglong2*)&Gs[(8 * ty + i) * 64 + 4 * k4];
#pragma unroll
            for (int j = 0; j < 4; j++) {
                acc[i][j] = fma2(gv.x, wv[j].x, acc[i][j]);
                acc[i][j] = fma2(gv.y, wv[j].y, acc[i][j]);
            }
        }
    }

    float y[8][4];
#pragma unroll
    for (int i = 0; i < 8; i++)
#pragma unroll
        for (int j = 0; j < 4; j++) {
            float2 uj = upk(acc[i][j]);
            y[i][j] = uj.x + uj.y;
        }

    const int bl = ty >> 1;
    const int plb = (ty & 1) * 8;
    float* ob = out + (long)(b0 + bl) * EE * PP + p0 + plb;
#pragma unroll
    for (int j = 0; j < 4; j++) {
        const int e = tx + 16 * j;
#pragma unroll
        for (int q = 0; q < 2; q++) {
            float4 v;
            v.x = y[4 * q + 0][j]; v.y = y[4 * q + 1][j];
            v.z = y[4 * q + 2][j]; v.w = y[4 * q + 3][j];
            *(float4*)&ob[(long)e * PP + 4 * q] = v;
        }
    }
}

// ============================================================================
extern "C" void kernel_launch(void* const* d_in, const int* in_sizes, int n_in,
                              void* d_out, int out_size) {
    (void)in_sizes; (void)n_in; (void)out_size;
    const float* x      = (const float*)d_in[0];
    const float* e_Wih0 = (const float*)d_in[1];
    const float* e_Whh0 = (const float*)d_in[2];
    const float* e_bih0 = (const float*)d_in[3];
    const float* e_bhh0 = (const float*)d_in[4];
    const float* e_Wih1 = (const float*)d_in[5];
    const float* e_Whh1 = (const float*)d_in[6];
    const float* e_bih1 = (const float*)d_in[7];
    const float* e_bhh1 = (const float*)d_in[8];
    // d_in[9] = t_Wih0: unused (transition input is zeros)
    const float* t_Whh0 = (const float*)d_in[10];
    const float* t_bih0 = (const float*)d_in[11];
    const float* t_bhh0 = (const float*)d_in[12];
    const float* t_Wih1 = (const float*)d_in[13];
    const float* t_Whh1 = (const float*)d_in[14];
    const float* t_bih1 = (const float*)d_in[15];
    const float* t_bhh1 = (const float*)d_in[16];
    const float* o_W1   = (const float*)d_in[17];
    const float* o_b1   = (const float*)d_in[18];
    const float* o_W2   = (const float*)d_in[19];
    const float* o_b2   = (const float*)d_in[20];
    float* out = (float*)d_out;

    cudaFuncSetAttribute(k_mlp, cudaFuncAttributeMaxDynamicSharedMemorySize,
                         MLP_SMEM_FLOATS * 4);

    k_z0<<<(BB * TT) / 64, 256>>>(x, e_Wih0, e_bih0, e_bhh0);
    k_scan<<<BB / 4, 128>>>(e_Whh0, e_Wih1, e_Whh1, e_bih1, e_bhh1,
                            t_Whh0, t_bih0, t_bhh0, t_Wih1, t_Whh1,
                            t_bih1, t_bhh1);
    dim3 g(PP / 16, BB / 8);
    k_mlp<<<g, 256, MLP_SMEM_FLOATS * 4>>>(o_W1, o_b1, o_W2, o_b2, out);
}